// round 7
// baseline (speedup 1.0000x reference)
#include <cuda_runtime.h>
#include <cuda_fp16.h>
#include <cstdint>
#include <math.h>

#define DIM    4096
#define B_ROWS 8192
#define EPS    1e-6f

// GEMM tiling
#define BM 128
#define BN 128
#define BK 32
#define NT 32                 // column tiles
#define MT 64                 // row tiles
#define ROWB  80              // fp16 smem row: 64B data + 16B pad
#define ROWB8 48              // fp8 smem row: 32B data + 16B pad (conflict-free ldsm)
#define TILE16_B (128 * ROWB)   // 10240
#define TILE8_B  (128 * ROWB8)  // 6144
#define A8_OFF   (2 * TILE16_B)            // 20480
#define B8_OFF   (A8_OFF + TILE8_B)        // 26624
#define STAGE_B  (2 * TILE16_B + 2 * TILE8_B)  // 32768
#define DYN_SMEM (2 * STAGE_B)             // 65536 -> 2 CTAs/SM

// ---------------- scratch (device globals; no runtime allocation) ----------
__device__ __half  g_xh[(size_t)B_ROWS * DIM];       // fp16(x)
__device__ uint8_t g_xe5[(size_t)B_ROWS * DIM];      // e5m2(x * 2^-8)
__device__ __half  g_whT[(size_t)DIM * DIM];         // W^T hi: [n][k] fp16
__device__ uint8_t g_wle5[(size_t)DIM * DIM];        // e5m2((W - fp16(W)) * 2^8), [n][k]
__device__ float g_h[(size_t)B_ROWS * DIM];
__device__ float g_psum[128 * DIM];
__device__ float g_psumsq[128 * DIM];
__device__ float g_mean[DIM];
__device__ float g_scale[DIM];

// ---------------- helpers ---------------------------------------------------
__device__ __forceinline__ uint32_t smem_u32(const void* p) {
    uint32_t a;
    asm("{ .reg .u64 t; cvta.to.shared.u64 t, %1; cvt.u32.u64 %0, t; }"
        : "=r"(a) : "l"(p));
    return a;
}

__device__ __forceinline__ uint32_t pk2(__half a, __half b) {
    return (uint32_t)__half_as_ushort(a) | ((uint32_t)__half_as_ushort(b) << 16);
}

// pack two floats to e5m2x2: result byte0 = lo, byte1 = hi
__device__ __forceinline__ uint16_t f2e5m2x2(float hi, float lo) {
    uint16_t r;
    asm("cvt.rn.satfinite.e5m2x2.f32 %0, %1, %2;" : "=h"(r) : "f"(hi), "f"(lo));
    return r;
}

#define CPA16(dst, src) \
    asm volatile("cp.async.cg.shared.global [%0], [%1], 16;" :: "r"(dst), "l"(src) : "memory")
#define CPA_COMMIT() asm volatile("cp.async.commit_group;" ::: "memory")
#define CPA_WAIT1()  asm volatile("cp.async.wait_group 1;" ::: "memory")
#define CPA_WAIT0()  asm volatile("cp.async.wait_group 0;" ::: "memory")

#define LDSM4(r0, r1, r2, r3, addr) \
    asm volatile("ldmatrix.sync.aligned.m8n8.x4.shared.b16 {%0,%1,%2,%3}, [%4];" \
        : "=r"(r0), "=r"(r1), "=r"(r2), "=r"(r3) : "r"(addr))

__device__ __forceinline__ void mma_fp16(float* c, const uint32_t* a, const uint32_t* b) {
    asm volatile(
        "mma.sync.aligned.m16n8k16.row.col.f32.f16.f16.f32 "
        "{%0,%1,%2,%3}, {%4,%5,%6,%7}, {%8,%9}, {%0,%1,%2,%3};"
        : "+f"(c[0]), "+f"(c[1]), "+f"(c[2]), "+f"(c[3])
        : "r"(a[0]), "r"(a[1]), "r"(a[2]), "r"(a[3]),
          "r"(b[0]), "r"(b[1]));
}

__device__ __forceinline__ void mma_e5m2(float* c, const uint32_t* a, const uint32_t* b) {
    asm volatile(
        "mma.sync.aligned.m16n8k32.row.col.f32.e5m2.e5m2.f32 "
        "{%0,%1,%2,%3}, {%4,%5,%6,%7}, {%8,%9}, {%0,%1,%2,%3};"
        : "+f"(c[0]), "+f"(c[1]), "+f"(c[2]), "+f"(c[3])
        : "r"(a[0]), "r"(a[1]), "r"(a[2]), "r"(a[3]),
          "r"(b[0]), "r"(b[1]));
}

// ---------------- prologue 1: x -> fp16 and e5m2(x/256) ---------------------
__global__ __launch_bounds__(256) void split_x_kernel(const float4* __restrict__ x)
{
    const size_t i = (size_t)blockIdx.x * 256 + threadIdx.x;
    const float4 v = x[i];
    uint2 H;
    H.x = pk2(__float2half_rn(v.x), __float2half_rn(v.y));
    H.y = pk2(__float2half_rn(v.z), __float2half_rn(v.w));
    ((uint2*)g_xh)[i] = H;
    const float s = 1.0f / 256.0f;
    const uint32_t e5 = (uint32_t)f2e5m2x2(v.y * s, v.x * s)
                      | ((uint32_t)f2e5m2x2(v.w * s, v.z * s) << 16);
    ((uint32_t*)g_xe5)[i] = e5;
}

// ---------------- prologue 2: W^T -> fp16 hi + e5m2(256*residual) -----------
__global__ __launch_bounds__(256) void split_w_kernel(
    const float* __restrict__ tw, const float* __restrict__ bbw)
{
    __shared__ float sw[32][33];
    const int tx = threadIdx.x & 31;
    const int ty = threadIdx.x >> 5;           // 0..7
    const int k0 = blockIdx.y * 32;
    const int n0 = blockIdx.x * 32;

    #pragma unroll
    for (int r = 0; r < 4; r++) {
        const int k = k0 + ty + r * 8;
        const int n = n0 + tx;
        const int kb = k >> 6, nb = n >> 6;
        float w = 0.0f;
        if (kb == nb)      { const float t = tw[(size_t)k * DIM + n]; w = t * t; }
        else if (kb < nb)  { w = bbw[(size_t)k * DIM + n]; }
        sw[ty + r * 8][tx] = w;
    }
    __syncthreads();
    #pragma unroll
    for (int r = 0; r < 4; r++) {
        const int n = n0 + ty + r * 8;
        const int k = k0 + tx;
        const float w = sw[tx][ty + r * 8];
        const __half h = __float2half_rn(w);
        const float lo = (w - __half2float(h)) * 256.0f;
        g_whT[(size_t)n * DIM + k]  = h;
        g_wle5[(size_t)n * DIM + k] = (uint8_t)(f2e5m2x2(0.0f, lo) & 0xFF);
    }
}

// ---------------- fp16 + fp8-correction GEMM: h = x @ W + x_init ------------
// Grid (NT, MT). CTA 128x128, BK=32, 2-stage cp.async pipeline, 2 CTAs/SM.
// Warp (wid>>2 = m half, wid&3 = n quarter): 64x32 warp tile.
// c += fp16(x)*fp16(W) ; c += e5m2(x/256)*e5m2(256*W_lo)   (product scale = 1)
__global__ __launch_bounds__(256, 2) void gemm_mma_kernel(const float* __restrict__ x_init)
{
    extern __shared__ char smc[];
    const uint32_t smb = smem_u32(smc);

    const int tid = threadIdx.x;
    const int wid = tid >> 5;
    const int lid = tid & 31;
    const int lane4 = lid >> 2;     // 0..7
    const int laneq = lid & 3;      // 0..3

    const int nt = (NT - 1) - blockIdx.x;   // heavy tiles first
    const int mt = blockIdx.y;
    const int m0 = mt * BM;
    const int n0 = nt * BN;
    const int KT = (nt + 1) * 4;    // k-tiles of 32

    const int m0w = (wid >> 2) * 64;
    const int n0w = (wid & 3) * 32;

    float c[4][4][4];
    #pragma unroll
    for (int i = 0; i < 4; i++)
        #pragma unroll
        for (int j = 0; j < 4; j++)
            #pragma unroll
            for (int q = 0; q < 4; q++)
                c[i][j][q] = 0.0f;

    // producer: 6 cp.async (16B) per thread per stage.
    // idx 0..1023:  fp16 tiles (0:Ah 1:Bh), row, 4 chunks
    // idx 1024..1535: fp8 tiles (0:Ae5 1:Ble5), row, 2 chunks
    auto issue_stage = [&](int kt, int s) {
        const int kof = kt * BK;
        const uint32_t sb = smb + (uint32_t)s * STAGE_B;
        #pragma unroll
        for (int it = 0; it < 6; it++) {
            const int idx = tid + it * 256;
            if (idx < 1024) {
                const int tile = idx >> 9;
                const int row  = (idx >> 2) & 127;
                const int ch   = idx & 3;
                const __half* base = tile ? g_whT : g_xh;
                const int row0     = tile ? n0 : m0;
                const __half* src = base + (size_t)(row0 + row) * DIM + kof + ch * 8;
                const uint32_t dst = sb + (uint32_t)(tile * TILE16_B + row * ROWB + ch * 16);
                CPA16(dst, src);
            } else {
                const int idx2 = idx - 1024;
                const int tile = idx2 >> 8;
                const int row  = (idx2 >> 1) & 127;
                const int ch   = idx2 & 1;
                const uint8_t* base = tile ? g_wle5 : g_xe5;
                const int row0      = tile ? n0 : m0;
                const uint8_t* src = base + (size_t)(row0 + row) * DIM + kof + ch * 16;
                const uint32_t dst = sb + (uint32_t)(A8_OFF + tile * TILE8_B
                                                     + row * ROWB8 + ch * 16);
                CPA16(dst, src);
            }
        }
        CPA_COMMIT();
    };

    // per-thread ldmatrix offsets (bytes within tile)
    const int L = lid;
    const uint32_t a_off  = (uint32_t)((m0w + (L & 15)) * ROWB + (L >> 4) * 16);
    const uint32_t b_off  = (uint32_t)((n0w + ((L >> 4) & 1) * 8 + (L & 7)) * ROWB
                                       + ((L >> 3) & 1) * 16);
    const uint32_t a8_off = (uint32_t)((m0w + (L & 15)) * ROWB8 + (L >> 4) * 16);
    const uint32_t b8_off = (uint32_t)((n0w + ((L >> 4) & 1) * 8 + (L & 7)) * ROWB8
                                       + ((L >> 3) & 1) * 16);

    issue_stage(0, 0);

    for (int kt = 0; kt < KT; kt++) {
        const int s = kt & 1;
        if (kt + 1 < KT) { issue_stage(kt + 1, s ^ 1); CPA_WAIT1(); }
        else             { CPA_WAIT0(); }
        __syncthreads();

        const uint32_t sb  = smb + (uint32_t)s * STAGE_B;
        const uint32_t sAh = sb;
        const uint32_t sBh = sb + TILE16_B;
        const uint32_t sA8 = sb + A8_OFF;
        const uint32_t sB8 = sb + B8_OFF;

        // ---- fp16 main pass (k16 x 2) ----
        #pragma unroll
        for (int ks = 0; ks < 2; ks++) {
            const uint32_t ko = (uint32_t)ks * 32;
            uint32_t bh[4][2];
            #pragma unroll
            for (int jp = 0; jp < 2; jp++) {
                const uint32_t bo = b_off + (uint32_t)jp * 16 * ROWB + ko;
                LDSM4(bh[jp*2][0], bh[jp*2][1], bh[jp*2+1][0], bh[jp*2+1][1], sBh + bo);
            }
            #pragma unroll
            for (int i = 0; i < 4; i++) {
                const uint32_t ao = a_off + (uint32_t)i * 16 * ROWB + ko;
                uint32_t ah[4];
                LDSM4(ah[0], ah[1], ah[2], ah[3], sAh + ao);
                #pragma unroll
                for (int j = 0; j < 4; j++)
                    mma_fp16(c[i][j], ah, bh[j]);
            }
        }

        // ---- fp8 correction pass (k32 x 1) ----
        {
            uint32_t b8[4][2];
            #pragma unroll
            for (int jp = 0; jp < 2; jp++) {
                const uint32_t bo = b8_off + (uint32_t)jp * 16 * ROWB8;
                LDSM4(b8[jp*2][0], b8[jp*2+1][0], b8[jp*2][1], b8[jp*2+1][1], sB8 + bo);
            }
            #pragma unroll
            for (int i = 0; i < 4; i++) {
                const uint32_t ao = a8_off + (uint32_t)i * 16 * ROWB8;
                uint32_t a8[4];
                LDSM4(a8[0], a8[1], a8[2], a8[3], sA8 + ao);
                #pragma unroll
                for (int j = 0; j < 4; j++)
                    mma_e5m2(c[i][j], a8, b8[j]);
            }
        }
        __syncthreads();
    }

    // epilogue: += x_init, store h
    #pragma unroll
    for (int i = 0; i < 4; i++) {
        const int row = m0 + m0w + i * 16 + lane4;
        #pragma unroll
        for (int j = 0; j < 4; j++) {
            const int col = n0 + n0w + j * 8 + laneq * 2;
            const size_t o0 = (size_t)row * DIM + col;
            const size_t o1 = (size_t)(row + 8) * DIM + col;
            const float2 x0 = *(const float2*)(x_init + o0);
            const float2 x1 = *(const float2*)(x_init + o1);
            float2 v0, v1;
            v0.x = c[i][j][0] + x0.x;
            v0.y = c[i][j][1] + x0.y;
            v1.x = c[i][j][2] + x1.x;
            v1.y = c[i][j][3] + x1.y;
            *(float2*)(g_h + o0) = v0;
            *(float2*)(g_h + o1) = v1;
        }
    }
}

// ---------------- stats stage 1: deterministic partial column sums ----------
__global__ __launch_bounds__(256) void stats1_kernel()
{
    const int c4  = blockIdx.x * 256 + threadIdx.x;   // 0..1023
    const int col = c4 * 4;
    const int rg  = blockIdx.y;                       // 0..127
    const int r0  = rg * 64;
    float4 s = {0.f, 0.f, 0.f, 0.f};
    float4 q = {0.f, 0.f, 0.f, 0.f};
    const float* p = g_h + (size_t)r0 * DIM + col;
    #pragma unroll 4
    for (int r = 0; r < 64; r++) {
        const float4 v = *(const float4*)(p + (size_t)r * DIM);
        s.x += v.x; q.x = fmaf(v.x, v.x, q.x);
        s.y += v.y; q.y = fmaf(v.y, v.y, q.y);
        s.z += v.z; q.z = fmaf(v.z, v.z, q.z);
        s.w += v.w; q.w = fmaf(v.w, v.w, q.w);
    }
    *(float4*)(g_psum + rg * DIM + col)   = s;
    *(float4*)(g_psumsq + rg * DIM + col) = q;
}

// ---------------- stats stage 2: finalize mean / scale ----------------------
__global__ __launch_bounds__(256) void stats2_kernel()
{
    const int col = blockIdx.x * 256 + threadIdx.x;
    float s = 0.0f, q = 0.0f;
    #pragma unroll 8
    for (int rg = 0; rg < 128; rg++) {
        s += g_psum[rg * DIM + col];
        q += g_psumsq[rg * DIM + col];
    }
    const float inv_n = 1.0f / (float)B_ROWS;
    const float mean  = s * inv_n;
    float var = q * inv_n - mean * mean;
    var = fmaxf(var, 0.0f);
    g_mean[col]  = mean;
    g_scale[col] = 1.0f / (sqrtf(var) + EPS);
}

// ---------------- normalize + sigmoid ---------------------------------------
__global__ __launch_bounds__(256) void final_kernel(float* __restrict__ out)
{
    const int row  = blockIdx.y;
    const int col  = (blockIdx.x * 256 + threadIdx.x) * 4;
    const size_t off = (size_t)row * DIM + col;

    const float4 h  = *(const float4*)(g_h + off);
    const float4 mu = *(const float4*)(g_mean + col);
    const float4 sc = *(const float4*)(g_scale + col);

    float4 o;
    o.x = 1.0f / (1.0f + expf(-(h.x - mu.x) * sc.x));
    o.y = 1.0f / (1.0f + expf(-(h.y - mu.y) * sc.y));
    o.z = 1.0f / (1.0f + expf(-(h.z - mu.z) * sc.z));
    o.w = 1.0f / (1.0f + expf(-(h.w - mu.w) * sc.w));
    *(float4*)(out + off) = o;
}

// ---------------- launcher ---------------------------------------------------
extern "C" void kernel_launch(void* const* d_in, const int* in_sizes, int n_in,
                              void* d_out, int out_size)
{
    const float* x   = (const float*)d_in[0];
    const float* xi  = (const float*)d_in[1];
    const float* tw  = (const float*)d_in[2];
    const float* bbw = (const float*)d_in[3];
    float* out = (float*)d_out;

    cudaFuncSetAttribute(gemm_mma_kernel,
                         cudaFuncAttributeMaxDynamicSharedMemorySize, DYN_SMEM);

    split_x_kernel<<<(B_ROWS * DIM) / (256 * 4), 256>>>((const float4*)x);
    split_w_kernel<<<dim3(DIM / 32, DIM / 32), 256>>>(tw, bbw);
    gemm_mma_kernel<<<dim3(NT, MT), 256, DYN_SMEM>>>(xi);
    stats1_kernel<<<dim3(4, 128), 256>>>();
    stats2_kernel<<<DIM / 256, 256>>>();
    final_kernel<<<dim3(DIM / (256 * 4), B_ROWS), 256>>>(out);
}

// round 8
// speedup vs baseline: 1.1971x; 1.1971x over previous
#include <cuda_runtime.h>
#include <cuda_fp16.h>
#include <cstdint>
#include <math.h>

#define DIM    4096
#define B_ROWS 8192
#define EPS    1e-6f

// GEMM tiling
#define BM 128
#define BN 128
#define BK 32
#define NT 32                 // column tiles
#define MT 64                 // row tiles
#define ROWB 80               // bytes per smem row (32 fp16 = 64B data + 16B pad)
#define TILE_B (128 * ROWB)   // 10240 bytes per operand tile
#define STAGE_B (3 * TILE_B)  // Ah, Bh, Bl = 30720 bytes
#define NSTAGE 3
#define DYN_SMEM (NSTAGE * STAGE_B)  // 92160 -> 2 CTAs/SM (184KB)

// ---------------- scratch (device globals; no runtime allocation) ----------
__device__ __half g_xh[(size_t)B_ROWS * DIM];        // fp16-rounded x
__device__ __half g_whT[(size_t)DIM * DIM];          // W^T hi: [n][k]
__device__ __half g_wlT[(size_t)DIM * DIM];          // W^T lo (fp16 residual)
__device__ float g_h[(size_t)B_ROWS * DIM];
__device__ float g_psum[128 * DIM];
__device__ float g_psumsq[128 * DIM];
__device__ float g_mean[DIM];
__device__ float g_scale[DIM];

// ---------------- helpers ---------------------------------------------------
__device__ __forceinline__ uint32_t smem_u32(const void* p) {
    uint32_t a;
    asm("{ .reg .u64 t; cvta.to.shared.u64 t, %1; cvt.u32.u64 %0, t; }"
        : "=r"(a) : "l"(p));
    return a;
}

__device__ __forceinline__ uint32_t pk2(__half a, __half b) {
    return (uint32_t)__half_as_ushort(a) | ((uint32_t)__half_as_ushort(b) << 16);
}

#define CPA16(dst, src) \
    asm volatile("cp.async.cg.shared.global [%0], [%1], 16;" :: "r"(dst), "l"(src) : "memory")
#define CPA_COMMIT() asm volatile("cp.async.commit_group;" ::: "memory")
#define CPA_WAIT1()  asm volatile("cp.async.wait_group 1;" ::: "memory")
#define CPA_WAIT0()  asm volatile("cp.async.wait_group 0;" ::: "memory")

#define LDSM4(r0, r1, r2, r3, addr) \
    asm volatile("ldmatrix.sync.aligned.m8n8.x4.shared.b16 {%0,%1,%2,%3}, [%4];" \
        : "=r"(r0), "=r"(r1), "=r"(r2), "=r"(r3) : "r"(addr))

__device__ __forceinline__ void mma_fp16(float* c, const uint32_t* a, const uint32_t* b) {
    asm volatile(
        "mma.sync.aligned.m16n8k16.row.col.f32.f16.f16.f32 "
        "{%0,%1,%2,%3}, {%4,%5,%6,%7}, {%8,%9}, {%0,%1,%2,%3};"
        : "+f"(c[0]), "+f"(c[1]), "+f"(c[2]), "+f"(c[3])
        : "r"(a[0]), "r"(a[1]), "r"(a[2]), "r"(a[3]),
          "r"(b[0]), "r"(b[1]));
}

// ---------------- prologue 1: round x to fp16 -------------------------------
__global__ __launch_bounds__(256) void split_x_kernel(const float4* __restrict__ x)
{
    const size_t i = (size_t)blockIdx.x * 256 + threadIdx.x;
    const float4 v = x[i];
    uint2 H;
    H.x = pk2(__float2half_rn(v.x), __float2half_rn(v.y));
    H.y = pk2(__float2half_rn(v.z), __float2half_rn(v.w));
    ((uint2*)g_xh)[i] = H;
}

// ---------------- prologue 2: build W^T (masked, squared diag), split hi/lo -
__global__ __launch_bounds__(256) void split_w_kernel(
    const float* __restrict__ tw, const float* __restrict__ bbw)
{
    __shared__ float sw[32][33];
    const int tx = threadIdx.x & 31;
    const int ty = threadIdx.x >> 5;           // 0..7
    const int k0 = blockIdx.y * 32;
    const int n0 = blockIdx.x * 32;

    #pragma unroll
    for (int r = 0; r < 4; r++) {
        const int k = k0 + ty + r * 8;
        const int n = n0 + tx;
        const int kb = k >> 6, nb = n >> 6;
        float w = 0.0f;
        if (kb == nb)      { const float t = tw[(size_t)k * DIM + n]; w = t * t; }
        else if (kb < nb)  { w = bbw[(size_t)k * DIM + n]; }
        sw[ty + r * 8][tx] = w;
    }
    __syncthreads();
    #pragma unroll
    for (int r = 0; r < 4; r++) {
        const int n = n0 + ty + r * 8;
        const int k = k0 + tx;
        const float w = sw[tx][ty + r * 8];
        const __half h = __float2half_rn(w);
        const __half l = __float2half_rn(w - __half2float(h));
        g_whT[(size_t)n * DIM + k] = h;
        g_wlT[(size_t)n * DIM + k] = l;
    }
}

// ---------------- fp16 2-pass mma.sync GEMM: h = x @ W + x_init -------------
// Grid (NT, MT). CTA 128x128, BK=32, 3-stage cp.async pipeline (1 sync/k-tile),
// 2 CTAs/SM. Warp (wid>>2 = m half, wid&3 = n quarter): 64x32 warp tile.
// Passes: c += Ah*Bh ; c += Ah*Bl
__global__ __launch_bounds__(256, 2) void gemm_mma_kernel(const float* __restrict__ x_init)
{
    extern __shared__ char smc[];
    const uint32_t smb = smem_u32(smc);

    const int tid = threadIdx.x;
    const int wid = tid >> 5;
    const int lid = tid & 31;
    const int lane4 = lid >> 2;     // 0..7
    const int laneq = lid & 3;      // 0..3

    const int nt = (NT - 1) - blockIdx.x;   // heavy tiles first
    const int mt = blockIdx.y;
    const int m0 = mt * BM;
    const int n0 = nt * BN;
    const int KT = (nt + 1) * 4;    // k-tiles of 32

    const int m0w = (wid >> 2) * 64;
    const int n0w = (wid & 3) * 32;

    float c[4][4][4];
    #pragma unroll
    for (int i = 0; i < 4; i++)
        #pragma unroll
        for (int j = 0; j < 4; j++)
            #pragma unroll
            for (int q = 0; q < 4; q++)
                c[i][j][q] = 0.0f;

    // producer: 6 cp.async (16B) per thread per stage.
    // idx -> tile (0:Ah 1:Bh 2:Bl), row (0..127), chunk (0..3)
    auto issue_stage = [&](int kt, int s) {
        const int kof = kt * BK;
        const uint32_t sb = smb + (uint32_t)s * STAGE_B;
        #pragma unroll
        for (int it = 0; it < 6; it++) {
            const int idx  = tid + it * 256;
            const int tile = idx >> 9;
            const int row  = (idx >> 2) & 127;
            const int ch   = idx & 3;
            const __half* base;
            int row0;
            if      (tile == 0) { base = g_xh;  row0 = m0; }
            else if (tile == 1) { base = g_whT; row0 = n0; }
            else                { base = g_wlT; row0 = n0; }
            const __half* src = base + (size_t)(row0 + row) * DIM + kof + ch * 8;
            const uint32_t dst = sb + (uint32_t)(tile * TILE_B + row * ROWB + ch * 16);
            CPA16(dst, src);
        }
        CPA_COMMIT();
    };

    // per-thread ldmatrix offset components (byte offsets within a tile)
    const int L = lid;
    const uint32_t a_off = (uint32_t)((m0w + (L & 15)) * ROWB + (L >> 4) * 16);
    const uint32_t b_off = (uint32_t)((n0w + ((L >> 4) & 1) * 8 + (L & 7)) * ROWB
                                      + ((L >> 3) & 1) * 16);

    issue_stage(0, 0);
    issue_stage(1, 1);

    int s  = 0;   // stage of k-tile kt
    int s2 = 2;   // stage of k-tile kt+2
    for (int kt = 0; kt < KT; kt++) {
        // stage kt complete when at most 1 newer group pending
        if (kt + 1 < KT) { CPA_WAIT1(); }
        else             { CPA_WAIT0(); }
        __syncthreads();

        // overwrite the buffer read two iterations ago (safe behind the sync)
        if (kt + 2 < KT) issue_stage(kt + 2, s2);

        const uint32_t sb  = smb + (uint32_t)s * STAGE_B;
        const uint32_t sAh = sb;
        const uint32_t sBh = sb + TILE_B;
        const uint32_t sBl = sb + 2 * TILE_B;

        #pragma unroll
        for (int ks = 0; ks < 2; ks++) {
            const uint32_t ko = (uint32_t)ks * 32;

            // B fragments: bh[j][2], bl[j][2] via 2 ldmatrix.x4 each
            uint32_t bh[4][2], bl[4][2];
            #pragma unroll
            for (int jp = 0; jp < 2; jp++) {
                const uint32_t bo = b_off + (uint32_t)jp * 16 * ROWB + ko;
                LDSM4(bh[jp*2][0], bh[jp*2][1], bh[jp*2+1][0], bh[jp*2+1][1], sBh + bo);
                LDSM4(bl[jp*2][0], bl[jp*2][1], bl[jp*2+1][0], bl[jp*2+1][1], sBl + bo);
            }
            // stream A fragments per i
            #pragma unroll
            for (int i = 0; i < 4; i++) {
                const uint32_t ao = a_off + (uint32_t)i * 16 * ROWB + ko;
                uint32_t ah[4];
                LDSM4(ah[0], ah[1], ah[2], ah[3], sAh + ao);
                #pragma unroll
                for (int j = 0; j < 4; j++) {
                    mma_fp16(c[i][j], ah, bh[j]);
                    mma_fp16(c[i][j], ah, bl[j]);
                }
            }
        }

        s  = (s  == NSTAGE - 1) ? 0 : s  + 1;
        s2 = (s2 == NSTAGE - 1) ? 0 : s2 + 1;
    }

    // epilogue: += x_init, store h
    #pragma unroll
    for (int i = 0; i < 4; i++) {
        const int row = m0 + m0w + i * 16 + lane4;
        #pragma unroll
        for (int j = 0; j < 4; j++) {
            const int col = n0 + n0w + j * 8 + laneq * 2;
            const size_t o0 = (size_t)row * DIM + col;
            const size_t o1 = (size_t)(row + 8) * DIM + col;
            const float2 x0 = *(const float2*)(x_init + o0);
            const float2 x1 = *(const float2*)(x_init + o1);
            float2 v0, v1;
            v0.x = c[i][j][0] + x0.x;
            v0.y = c[i][j][1] + x0.y;
            v1.x = c[i][j][2] + x1.x;
            v1.y = c[i][j][3] + x1.y;
            *(float2*)(g_h + o0) = v0;
            *(float2*)(g_h + o1) = v1;
        }
    }
}

// ---------------- stats stage 1: deterministic partial column sums ----------
// grid (4, 128): thread owns 4 columns (float4) over 64 rows; fixed slots.
__global__ __launch_bounds__(256) void stats1_kernel()
{
    const int c4  = blockIdx.x * 256 + threadIdx.x;   // 0..1023
    const int col = c4 * 4;
    const int rg  = blockIdx.y;                       // 0..127
    const int r0  = rg * 64;
    float4 s = {0.f, 0.f, 0.f, 0.f};
    float4 q = {0.f, 0.f, 0.f, 0.f};
    const float* p = g_h + (size_t)r0 * DIM + col;
    #pragma unroll 4
    for (int r = 0; r < 64; r++) {
        const float4 v = *(const float4*)(p + (size_t)r * DIM);
        s.x += v.x; q.x = fmaf(v.x, v.x, q.x);
        s.y += v.y; q.y = fmaf(v.y, v.y, q.y);
        s.z += v.z; q.z = fmaf(v.z, v.z, q.z);
        s.w += v.w; q.w = fmaf(v.w, v.w, q.w);
    }
    *(float4*)(g_psum + rg * DIM + col)   = s;
    *(float4*)(g_psumsq + rg * DIM + col) = q;
}

// ---------------- stats stage 2: finalize mean / scale ----------------------
__global__ __launch_bounds__(256) void stats2_kernel()
{
    const int col = blockIdx.x * 256 + threadIdx.x;
    float s = 0.0f, q = 0.0f;
    #pragma unroll 8
    for (int rg = 0; rg < 128; rg++) {
        s += g_psum[rg * DIM + col];
        q += g_psumsq[rg * DIM + col];
    }
    const float inv_n = 1.0f / (float)B_ROWS;
    const float mean  = s * inv_n;
    float var = q * inv_n - mean * mean;
    var = fmaxf(var, 0.0f);
    g_mean[col]  = mean;
    g_scale[col] = 1.0f / (sqrtf(var) + EPS);
}

// ---------------- normalize + sigmoid ---------------------------------------
__global__ __launch_bounds__(256) void final_kernel(float* __restrict__ out)
{
    const int row  = blockIdx.y;
    const int col  = (blockIdx.x * 256 + threadIdx.x) * 4;
    const size_t off = (size_t)row * DIM + col;

    const float4 h  = *(const float4*)(g_h + off);
    const float4 mu = *(const float4*)(g_mean + col);
    const float4 sc = *(const float4*)(g_scale + col);

    float4 o;
    o.x = 1.0f / (1.0f + expf(-(h.x - mu.x) * sc.x));
    o.y = 1.0f / (1.0f + expf(-(h.y - mu.y) * sc.y));
    o.z = 1.0f / (1.0f + expf(-(h.z - mu.z) * sc.z));
    o.w = 1.0f / (1.0f + expf(-(h.w - mu.w) * sc.w));
    *(float4*)(out + off) = o;
}

// ---------------- launcher ---------------------------------------------------
extern "C" void kernel_launch(void* const* d_in, const int* in_sizes, int n_in,
                              void* d_out, int out_size)
{
    const float* x   = (const float*)d_in[0];
    const float* xi  = (const float*)d_in[1];
    const float* tw  = (const float*)d_in[2];
    const float* bbw = (const float*)d_in[3];
    float* out = (float*)d_out;

    cudaFuncSetAttribute(gemm_mma_kernel,
                         cudaFuncAttributeMaxDynamicSharedMemorySize, DYN_SMEM);

    split_x_kernel<<<(B_ROWS * DIM) / (256 * 4), 256>>>((const float4*)x);
    split_w_kernel<<<dim3(DIM / 32, DIM / 32), 256>>>(tw, bbw);
    gemm_mma_kernel<<<dim3(NT, MT), 256, DYN_SMEM>>>(xi);
    stats1_kernel<<<dim3(4, 128), 256>>>();
    stats2_kernel<<<DIM / 256, 256>>>();
    final_kernel<<<dim3(DIM / (256 * 4), B_ROWS), 256>>>(out);
}

// round 9
// speedup vs baseline: 1.8911x; 1.5798x over previous
#include <cuda_runtime.h>
#include <cuda_fp16.h>
#include <cstdint>
#include <math.h>

#define DIM    4096
#define B_ROWS 8192
#define EPS    1e-6f

// GEMM tiling
#define BM 128
#define BN 128
#define BK 32
#define NT 32                 // column tiles
#define MT 64                 // row tiles
#define ROWB 80               // bytes per smem row (32 fp16 = 64B data + 16B pad)
#define TILE_B (128 * ROWB)   // 10240 bytes per operand tile
#define STAGE_B (2 * TILE_B)  // Ah, Bh = 20480 bytes
#define NSTAGE 4
#define DYN_SMEM (NSTAGE * STAGE_B)  // 81920 -> 2 CTAs/SM (164KB)

// ---------------- scratch (device globals; no runtime allocation) ----------
__device__ __half g_xh[(size_t)B_ROWS * DIM];        // fp16-rounded x
__device__ __half g_whT[(size_t)DIM * DIM];          // W^T: [n][k] fp16
__device__ float g_h[(size_t)B_ROWS * DIM];
__device__ float g_psum[128 * DIM];
__device__ float g_psumsq[128 * DIM];
__device__ float g_mean[DIM];
__device__ float g_scale[DIM];

// ---------------- helpers ---------------------------------------------------
__device__ __forceinline__ uint32_t smem_u32(const void* p) {
    uint32_t a;
    asm("{ .reg .u64 t; cvta.to.shared.u64 t, %1; cvt.u32.u64 %0, t; }"
        : "=r"(a) : "l"(p));
    return a;
}

__device__ __forceinline__ uint32_t pk2(__half a, __half b) {
    return (uint32_t)__half_as_ushort(a) | ((uint32_t)__half_as_ushort(b) << 16);
}

#define CPA16(dst, src) \
    asm volatile("cp.async.cg.shared.global [%0], [%1], 16;" :: "r"(dst), "l"(src) : "memory")
#define CPA_COMMIT() asm volatile("cp.async.commit_group;" ::: "memory")
#define CPA_WAIT2()  asm volatile("cp.async.wait_group 2;" ::: "memory")
#define CPA_WAIT1()  asm volatile("cp.async.wait_group 1;" ::: "memory")
#define CPA_WAIT0()  asm volatile("cp.async.wait_group 0;" ::: "memory")

#define LDSM4(r0, r1, r2, r3, addr) \
    asm volatile("ldmatrix.sync.aligned.m8n8.x4.shared.b16 {%0,%1,%2,%3}, [%4];" \
        : "=r"(r0), "=r"(r1), "=r"(r2), "=r"(r3) : "r"(addr))

__device__ __forceinline__ void mma_fp16(float* c, const uint32_t* a, const uint32_t* b) {
    asm volatile(
        "mma.sync.aligned.m16n8k16.row.col.f32.f16.f16.f32 "
        "{%0,%1,%2,%3}, {%4,%5,%6,%7}, {%8,%9}, {%0,%1,%2,%3};"
        : "+f"(c[0]), "+f"(c[1]), "+f"(c[2]), "+f"(c[3])
        : "r"(a[0]), "r"(a[1]), "r"(a[2]), "r"(a[3]),
          "r"(b[0]), "r"(b[1]));
}

// ---------------- prologue 1: round x to fp16 -------------------------------
__global__ __launch_bounds__(256) void split_x_kernel(const float4* __restrict__ x)
{
    const size_t i = (size_t)blockIdx.x * 256 + threadIdx.x;
    const float4 v = x[i];
    uint2 H;
    H.x = pk2(__float2half_rn(v.x), __float2half_rn(v.y));
    H.y = pk2(__float2half_rn(v.z), __float2half_rn(v.w));
    ((uint2*)g_xh)[i] = H;
}

// ---------------- prologue 2: build W^T (masked, squared diag) fp16 ---------
__global__ __launch_bounds__(256) void split_w_kernel(
    const float* __restrict__ tw, const float* __restrict__ bbw)
{
    __shared__ float sw[32][33];
    const int tx = threadIdx.x & 31;
    const int ty = threadIdx.x >> 5;           // 0..7
    const int k0 = blockIdx.y * 32;
    const int n0 = blockIdx.x * 32;

    #pragma unroll
    for (int r = 0; r < 4; r++) {
        const int k = k0 + ty + r * 8;
        const int n = n0 + tx;
        const int kb = k >> 6, nb = n >> 6;
        float w = 0.0f;
        if (kb == nb)      { const float t = tw[(size_t)k * DIM + n]; w = t * t; }
        else if (kb < nb)  { w = bbw[(size_t)k * DIM + n]; }
        sw[ty + r * 8][tx] = w;
    }
    __syncthreads();
    #pragma unroll
    for (int r = 0; r < 4; r++) {
        const int n = n0 + ty + r * 8;
        const int k = k0 + tx;
        g_whT[(size_t)n * DIM + k] = __float2half_rn(sw[tx][ty + r * 8]);
    }
}

// ---------------- fp16 single-pass mma.sync GEMM: h = x @ W + x_init --------
// Grid (NT, MT). CTA 128x128, BK=32, 4-stage cp.async pipeline (1 sync/k-tile),
// 2 CTAs/SM. Warp (wid>>2 = m half, wid&3 = n quarter): 64x32 warp tile.
__global__ __launch_bounds__(256, 2) void gemm_mma_kernel(const float* __restrict__ x_init)
{
    extern __shared__ char smc[];
    const uint32_t smb = smem_u32(smc);

    const int tid = threadIdx.x;
    const int wid = tid >> 5;
    const int lid = tid & 31;
    const int lane4 = lid >> 2;     // 0..7
    const int laneq = lid & 3;      // 0..3

    const int nt = (NT - 1) - blockIdx.x;   // heavy tiles first
    const int mt = blockIdx.y;
    const int m0 = mt * BM;
    const int n0 = nt * BN;
    const int KT = (nt + 1) * 4;    // k-tiles of 32

    const int m0w = (wid >> 2) * 64;
    const int n0w = (wid & 3) * 32;

    float c[4][4][4];
    #pragma unroll
    for (int i = 0; i < 4; i++)
        #pragma unroll
        for (int j = 0; j < 4; j++)
            #pragma unroll
            for (int q = 0; q < 4; q++)
                c[i][j][q] = 0.0f;

    // producer: 4 cp.async (16B) per thread per stage.
    // idx -> tile (0:Ah 1:Bh), row (0..127), chunk (0..3)
    auto issue_stage = [&](int kt, int s) {
        const int kof = kt * BK;
        const uint32_t sb = smb + (uint32_t)s * STAGE_B;
        #pragma unroll
        for (int it = 0; it < 4; it++) {
            const int idx  = tid + it * 256;
            const int tile = idx >> 9;
            const int row  = (idx >> 2) & 127;
            const int ch   = idx & 3;
            const __half* base = tile ? g_whT : g_xh;
            const int row0     = tile ? n0 : m0;
            const __half* src = base + (size_t)(row0 + row) * DIM + kof + ch * 8;
            const uint32_t dst = sb + (uint32_t)(tile * TILE_B + row * ROWB + ch * 16);
            CPA16(dst, src);
        }
        CPA_COMMIT();
    };

    // per-thread ldmatrix offset components (byte offsets within a tile)
    const int L = lid;
    const uint32_t a_off = (uint32_t)((m0w + (L & 15)) * ROWB + (L >> 4) * 16);
    const uint32_t b_off = (uint32_t)((n0w + ((L >> 4) & 1) * 8 + (L & 7)) * ROWB
                                      + ((L >> 3) & 1) * 16);

    // prologue: fill 3 stages (KT >= 4 always)
    issue_stage(0, 0);
    issue_stage(1, 1);
    issue_stage(2, 2);

    int s  = 0;              // stage of k-tile kt
    int s3 = NSTAGE - 1;     // stage of k-tile kt+3
    for (int kt = 0; kt < KT; kt++) {
        // wait until stage kt has landed (pending groups = min(KT-kt-1, 2))
        const int rem = KT - kt - 1;
        if      (rem >= 2) { CPA_WAIT2(); }
        else if (rem == 1) { CPA_WAIT1(); }
        else               { CPA_WAIT0(); }
        __syncthreads();

        // refill the slot read at iteration kt-1 (safe behind the sync)
        if (kt + 3 < KT) issue_stage(kt + 3, s3);

        const uint32_t sb  = smb + (uint32_t)s * STAGE_B;
        const uint32_t sAh = sb;
        const uint32_t sBh = sb + TILE_B;

        #pragma unroll
        for (int ks = 0; ks < 2; ks++) {
            const uint32_t ko = (uint32_t)ks * 32;

            uint32_t bh[4][2];
            #pragma unroll
            for (int jp = 0; jp < 2; jp++) {
                const uint32_t bo = b_off + (uint32_t)jp * 16 * ROWB + ko;
                LDSM4(bh[jp*2][0], bh[jp*2][1], bh[jp*2+1][0], bh[jp*2+1][1], sBh + bo);
            }
            #pragma unroll
            for (int i = 0; i < 4; i++) {
                const uint32_t ao = a_off + (uint32_t)i * 16 * ROWB + ko;
                uint32_t ah[4];
                LDSM4(ah[0], ah[1], ah[2], ah[3], sAh + ao);
                #pragma unroll
                for (int j = 0; j < 4; j++)
                    mma_fp16(c[i][j], ah, bh[j]);
            }
        }

        s  = (s  == NSTAGE - 1) ? 0 : s  + 1;
        s3 = (s3 == NSTAGE - 1) ? 0 : s3 + 1;
    }

    // epilogue: += x_init, store h
    #pragma unroll
    for (int i = 0; i < 4; i++) {
        const int row = m0 + m0w + i * 16 + lane4;
        #pragma unroll
        for (int j = 0; j < 4; j++) {
            const int col = n0 + n0w + j * 8 + laneq * 2;
            const size_t o0 = (size_t)row * DIM + col;
            const size_t o1 = (size_t)(row + 8) * DIM + col;
            const float2 x0 = *(const float2*)(x_init + o0);
            const float2 x1 = *(const float2*)(x_init + o1);
            float2 v0, v1;
            v0.x = c[i][j][0] + x0.x;
            v0.y = c[i][j][1] + x0.y;
            v1.x = c[i][j][2] + x1.x;
            v1.y = c[i][j][3] + x1.y;
            *(float2*)(g_h + o0) = v0;
            *(float2*)(g_h + o1) = v1;
        }
    }
}

// ---------------- stats stage 1: deterministic partial column sums ----------
// grid (4, 128): thread owns 4 columns (float4) over 64 rows; fixed slots.
__global__ __launch_bounds__(256) void stats1_kernel()
{
    const int c4  = blockIdx.x * 256 + threadIdx.x;   // 0..1023
    const int col = c4 * 4;
    const int rg  = blockIdx.y;                       // 0..127
    const int r0  = rg * 64;
    float4 s = {0.f, 0.f, 0.f, 0.f};
    float4 q = {0.f, 0.f, 0.f, 0.f};
    const float* p = g_h + (size_t)r0 * DIM + col;
    #pragma unroll 4
    for (int r = 0; r < 64; r++) {
        const float4 v = *(const float4*)(p + (size_t)r * DIM);
        s.x += v.x; q.x = fmaf(v.x, v.x, q.x);
        s.y += v.y; q.y = fmaf(v.y, v.y, q.y);
        s.z += v.z; q.z = fmaf(v.z, v.z, q.z);
        s.w += v.w; q.w = fmaf(v.w, v.w, q.w);
    }
    *(float4*)(g_psum + rg * DIM + col)   = s;
    *(float4*)(g_psumsq + rg * DIM + col) = q;
}

// ---------------- stats stage 2: finalize mean / scale ----------------------
__global__ __launch_bounds__(256) void stats2_kernel()
{
    const int col = blockIdx.x * 256 + threadIdx.x;
    float s = 0.0f, q = 0.0f;
    #pragma unroll 8
    for (int rg = 0; rg < 128; rg++) {
        s += g_psum[rg * DIM + col];
        q += g_psumsq[rg * DIM + col];
    }
    const float inv_n = 1.0f / (float)B_ROWS;
    const float mean  = s * inv_n;
    float var = q * inv_n - mean * mean;
    var = fmaxf(var, 0.0f);
    g_mean[col]  = mean;
    g_scale[col] = 1.0f / (sqrtf(var) + EPS);
}

// ---------------- normalize + sigmoid ---------------------------------------
__global__ __launch_bounds__(256) void final_kernel(float* __restrict__ out)
{
    const int row  = blockIdx.y;
    const int col  = (blockIdx.x * 256 + threadIdx.x) * 4;
    const size_t off = (size_t)row * DIM + col;

    const float4 h  = *(const float4*)(g_h + off);
    const float4 mu = *(const float4*)(g_mean + col);
    const float4 sc = *(const float4*)(g_scale + col);

    float4 o;
    o.x = 1.0f / (1.0f + expf(-(h.x - mu.x) * sc.x));
    o.y = 1.0f / (1.0f + expf(-(h.y - mu.y) * sc.y));
    o.z = 1.0f / (1.0f + expf(-(h.z - mu.z) * sc.z));
    o.w = 1.0f / (1.0f + expf(-(h.w - mu.w) * sc.w));
    *(float4*)(out + off) = o;
}

// ---------------- launcher ---------------------------------------------------
extern "C" void kernel_launch(void* const* d_in, const int* in_sizes, int n_in,
                              void* d_out, int out_size)
{
    const float* x   = (const float*)d_in[0];
    const float* xi  = (const float*)d_in[1];
    const float* tw  = (const float*)d_in[2];
    const float* bbw = (const float*)d_in[3];
    float* out = (float*)d_out;

    cudaFuncSetAttribute(gemm_mma_kernel,
                         cudaFuncAttributeMaxDynamicSharedMemorySize, DYN_SMEM);

    split_x_kernel<<<(B_ROWS * DIM) / (256 * 4), 256>>>((const float4*)x);
    split_w_kernel<<<dim3(DIM / 32, DIM / 32), 256>>>(tw, bbw);
    gemm_mma_kernel<<<dim3(NT, MT), 256, DYN_SMEM>>>(xi);
    stats1_kernel<<<dim3(4, 128), 256>>>();
    stats2_kernel<<<DIM / 256, 256>>>();
    final_kernel<<<dim3(DIM / (256 * 4), B_ROWS), 256>>>(out);
}

// round 10
// speedup vs baseline: 2.1391x; 1.1311x over previous
#include <cuda_runtime.h>
#include <cuda_fp16.h>
#include <cstdint>
#include <math.h>

#define DIM    4096
#define B_ROWS 8192
#define EPS    1e-6f

// GEMM tiling
#define BM 128
#define BN 128
#define BK 32
#define NT 32                 // column tiles
#define MT 64                 // row tiles
#define ROWB 80               // bytes per smem row (32 fp16 = 64B data + 16B pad)
#define TILE_B (128 * ROWB)   // 10240 bytes per operand tile
#define STAGE_B (2 * TILE_B)  // Ah, Bh = 20480 bytes
#define NSTAGE 4
#define DYN_SMEM (NSTAGE * STAGE_B)  // 81920 -> 2 CTAs/SM (164KB)

// ---------------- scratch (device globals; no runtime allocation) ----------
__device__ __half g_xh[(size_t)B_ROWS * DIM];        // fp16-rounded x
__device__ __half g_whT[(size_t)DIM * DIM];          // W^T: [n][k] fp16
__device__ float g_h[(size_t)B_ROWS * DIM];
__device__ float g_psum[128 * DIM];
__device__ float g_psumsq[128 * DIM];
__device__ float g_mean[DIM];
__device__ float g_scale[DIM];

// ---------------- helpers ---------------------------------------------------
__device__ __forceinline__ uint32_t smem_u32(const void* p) {
    uint32_t a;
    asm("{ .reg .u64 t; cvta.to.shared.u64 t, %1; cvt.u32.u64 %0, t; }"
        : "=r"(a) : "l"(p));
    return a;
}

__device__ __forceinline__ uint32_t pk2(__half a, __half b) {
    return (uint32_t)__half_as_ushort(a) | ((uint32_t)__half_as_ushort(b) << 16);
}

#define CPA16(dst, src) \
    asm volatile("cp.async.cg.shared.global [%0], [%1], 16;" :: "r"(dst), "l"(src) : "memory")
#define CPA_COMMIT() asm volatile("cp.async.commit_group;" ::: "memory")
#define CPA_WAIT2()  asm volatile("cp.async.wait_group 2;" ::: "memory")
#define CPA_WAIT1()  asm volatile("cp.async.wait_group 1;" ::: "memory")
#define CPA_WAIT0()  asm volatile("cp.async.wait_group 0;" ::: "memory")

#define LDSM4(r0, r1, r2, r3, addr) \
    asm volatile("ldmatrix.sync.aligned.m8n8.x4.shared.b16 {%0,%1,%2,%3}, [%4];" \
        : "=r"(r0), "=r"(r1), "=r"(r2), "=r"(r3) : "r"(addr))

__device__ __forceinline__ void mma_fp16(float* c, const uint32_t* a, const uint32_t* b) {
    asm volatile(
        "mma.sync.aligned.m16n8k16.row.col.f32.f16.f16.f32 "
        "{%0,%1,%2,%3}, {%4,%5,%6,%7}, {%8,%9}, {%0,%1,%2,%3};"
        : "+f"(c[0]), "+f"(c[1]), "+f"(c[2]), "+f"(c[3])
        : "r"(a[0]), "r"(a[1]), "r"(a[2]), "r"(a[3]),
          "r"(b[0]), "r"(b[1]));
}

// ---------------- prologue 1: round x to fp16 -------------------------------
__global__ __launch_bounds__(256) void split_x_kernel(const float4* __restrict__ x)
{
    const size_t i = (size_t)blockIdx.x * 256 + threadIdx.x;
    const float4 v = x[i];
    uint2 H;
    H.x = pk2(__float2half_rn(v.x), __float2half_rn(v.y));
    H.y = pk2(__float2half_rn(v.z), __float2half_rn(v.w));
    ((uint2*)g_xh)[i] = H;
}

// ---------------- prologue 2: build W^T (masked, squared diag) fp16 ---------
__global__ __launch_bounds__(256) void split_w_kernel(
    const float* __restrict__ tw, const float* __restrict__ bbw)
{
    __shared__ float sw[32][33];
    const int tx = threadIdx.x & 31;
    const int ty = threadIdx.x >> 5;           // 0..7
    const int k0 = blockIdx.y * 32;
    const int n0 = blockIdx.x * 32;

    #pragma unroll
    for (int r = 0; r < 4; r++) {
        const int k = k0 + ty + r * 8;
        const int n = n0 + tx;
        const int kb = k >> 6, nb = n >> 6;
        float w = 0.0f;
        if (kb == nb)      { const float t = tw[(size_t)k * DIM + n]; w = t * t; }
        else if (kb < nb)  { w = bbw[(size_t)k * DIM + n]; }
        sw[ty + r * 8][tx] = w;
    }
    __syncthreads();
    #pragma unroll
    for (int r = 0; r < 4; r++) {
        const int n = n0 + ty + r * 8;
        const int k = k0 + tx;
        g_whT[(size_t)n * DIM + k] = __float2half_rn(sw[tx][ty + r * 8]);
    }
}

// ---------------- fp16 single-pass mma.sync GEMM: h = x @ W + x_init --------
// Grid (NT, MT). CTA 128x128, 128 threads (4 warps), warp tile 64x64.
// BK=32, 4-stage cp.async pipeline (1 sync/k-tile), 2 CTAs/SM.
// Warp (wid>>1 = m half, wid&1 = n half).
__global__ __launch_bounds__(128, 2) void gemm_mma_kernel(const float* __restrict__ x_init)
{
    extern __shared__ char smc[];
    const uint32_t smb = smem_u32(smc);

    const int tid = threadIdx.x;
    const int wid = tid >> 5;
    const int lid = tid & 31;
    const int lane4 = lid >> 2;     // 0..7
    const int laneq = lid & 3;      // 0..3

    const int nt = (NT - 1) - blockIdx.x;   // heavy tiles first
    const int mt = blockIdx.y;
    const int m0 = mt * BM;
    const int n0 = nt * BN;
    const int KT = (nt + 1) * 4;    // k-tiles of 32

    const int m0w = (wid >> 1) * 64;
    const int n0w = (wid & 1) * 64;

    float c[4][8][4];
    #pragma unroll
    for (int i = 0; i < 4; i++)
        #pragma unroll
        for (int j = 0; j < 8; j++)
            #pragma unroll
            for (int q = 0; q < 4; q++)
                c[i][j][q] = 0.0f;

    // producer: 8 cp.async (16B) per thread per stage.
    // idx -> tile (0:Ah 1:Bh), row (0..127), chunk (0..3)
    auto issue_stage = [&](int kt, int s) {
        const int kof = kt * BK;
        const uint32_t sb = smb + (uint32_t)s * STAGE_B;
        #pragma unroll
        for (int it = 0; it < 8; it++) {
            const int idx  = tid + it * 128;
            const int tile = idx >> 9;
            const int row  = (idx >> 2) & 127;
            const int ch   = idx & 3;
            const __half* base = tile ? g_whT : g_xh;
            const int row0     = tile ? n0 : m0;
            const __half* src = base + (size_t)(row0 + row) * DIM + kof + ch * 8;
            const uint32_t dst = sb + (uint32_t)(tile * TILE_B + row * ROWB + ch * 16);
            CPA16(dst, src);
        }
        CPA_COMMIT();
    };

    // per-thread ldmatrix offset components (byte offsets within a tile)
    const int L = lid;
    const uint32_t a_off = (uint32_t)((m0w + (L & 15)) * ROWB + (L >> 4) * 16);
    const uint32_t b_off = (uint32_t)((n0w + ((L >> 4) & 1) * 8 + (L & 7)) * ROWB
                                      + ((L >> 3) & 1) * 16);

    // prologue: fill 3 stages (KT >= 4 always)
    issue_stage(0, 0);
    issue_stage(1, 1);
    issue_stage(2, 2);

    int s  = 0;              // stage of k-tile kt
    int s3 = NSTAGE - 1;     // stage of k-tile kt+3
    for (int kt = 0; kt < KT; kt++) {
        // wait until stage kt has landed (pending groups = min(KT-kt-1, 2))
        const int rem = KT - kt - 1;
        if      (rem >= 2) { CPA_WAIT2(); }
        else if (rem == 1) { CPA_WAIT1(); }
        else               { CPA_WAIT0(); }
        __syncthreads();

        // refill the slot read at iteration kt-1 (safe behind the sync)
        if (kt + 3 < KT) issue_stage(kt + 3, s3);

        const uint32_t sb  = smb + (uint32_t)s * STAGE_B;
        const uint32_t sAh = sb;
        const uint32_t sBh = sb + TILE_B;

        #pragma unroll
        for (int ks = 0; ks < 2; ks++) {
            const uint32_t ko = (uint32_t)ks * 32;

            // B fragments: 64 cols = 8 n8 frags via 4 ldmatrix.x4
            uint32_t bh[8][2];
            #pragma unroll
            for (int jp = 0; jp < 4; jp++) {
                const uint32_t bo = b_off + (uint32_t)jp * 16 * ROWB + ko;
                LDSM4(bh[jp*2][0], bh[jp*2][1], bh[jp*2+1][0], bh[jp*2+1][1], sBh + bo);
            }
            // stream A fragments per i; each feeds 8 mma
            #pragma unroll
            for (int i = 0; i < 4; i++) {
                const uint32_t ao = a_off + (uint32_t)i * 16 * ROWB + ko;
                uint32_t ah[4];
                LDSM4(ah[0], ah[1], ah[2], ah[3], sAh + ao);
                #pragma unroll
                for (int j = 0; j < 8; j++)
                    mma_fp16(c[i][j], ah, bh[j]);
            }
        }

        s  = (s  == NSTAGE - 1) ? 0 : s  + 1;
        s3 = (s3 == NSTAGE - 1) ? 0 : s3 + 1;
    }

    // epilogue: += x_init, store h
    #pragma unroll
    for (int i = 0; i < 4; i++) {
        const int row = m0 + m0w + i * 16 + lane4;
        #pragma unroll
        for (int j = 0; j < 8; j++) {
            const int col = n0 + n0w + j * 8 + laneq * 2;
            const size_t o0 = (size_t)row * DIM + col;
            const size_t o1 = (size_t)(row + 8) * DIM + col;
            const float2 x0 = *(const float2*)(x_init + o0);
            const float2 x1 = *(const float2*)(x_init + o1);
            float2 v0, v1;
            v0.x = c[i][j][0] + x0.x;
            v0.y = c[i][j][1] + x0.y;
            v1.x = c[i][j][2] + x1.x;
            v1.y = c[i][j][3] + x1.y;
            *(float2*)(g_h + o0) = v0;
            *(float2*)(g_h + o1) = v1;
        }
    }
}

// ---------------- stats stage 1: deterministic partial column sums ----------
// grid (4, 128): thread owns 4 columns (float4) over 64 rows; fixed slots.
__global__ __launch_bounds__(256) void stats1_kernel()
{
    const int c4  = blockIdx.x * 256 + threadIdx.x;   // 0..1023
    const int col = c4 * 4;
    const int rg  = blockIdx.y;                       // 0..127
    const int r0  = rg * 64;
    float4 s = {0.f, 0.f, 0.f, 0.f};
    float4 q = {0.f, 0.f, 0.f, 0.f};
    const float* p = g_h + (size_t)r0 * DIM + col;
    #pragma unroll 4
    for (int r = 0; r < 64; r++) {
        const float4 v = *(const float4*)(p + (size_t)r * DIM);
        s.x += v.x; q.x = fmaf(v.x, v.x, q.x);
        s.y += v.y; q.y = fmaf(v.y, v.y, q.y);
        s.z += v.z; q.z = fmaf(v.z, v.z, q.z);
        s.w += v.w; q.w = fmaf(v.w, v.w, q.w);
    }
    *(float4*)(g_psum + rg * DIM + col)   = s;
    *(float4*)(g_psumsq + rg * DIM + col) = q;
}

// ---------------- stats stage 2: finalize mean / scale ----------------------
__global__ __launch_bounds__(256) void stats2_kernel()
{
    const int col = blockIdx.x * 256 + threadIdx.x;
    float s = 0.0f, q = 0.0f;
    #pragma unroll 8
    for (int rg = 0; rg < 128; rg++) {
        s += g_psum[rg * DIM + col];
        q += g_psumsq[rg * DIM + col];
    }
    const float inv_n = 1.0f / (float)B_ROWS;
    const float mean  = s * inv_n;
    float var = q * inv_n - mean * mean;
    var = fmaxf(var, 0.0f);
    g_mean[col]  = mean;
    g_scale[col] = 1.0f / (sqrtf(var) + EPS);
}

// ---------------- normalize + sigmoid ---------------------------------------
__global__ __launch_bounds__(256) void final_kernel(float* __restrict__ out)
{
    const int row  = blockIdx.y;
    const int col  = (blockIdx.x * 256 + threadIdx.x) * 4;
    const size_t off = (size_t)row * DIM + col;

    const float4 h  = *(const float4*)(g_h + off);
    const float4 mu = *(const float4*)(g_mean + col);
    const float4 sc = *(const float4*)(g_scale + col);

    float4 o;
    o.x = 1.0f / (1.0f + expf(-(h.x - mu.x) * sc.x));
    o.y = 1.0f / (1.0f + expf(-(h.y - mu.y) * sc.y));
    o.z = 1.0f / (1.0f + expf(-(h.z - mu.z) * sc.z));
    o.w = 1.0f / (1.0f + expf(-(h.w - mu.w) * sc.w));
    *(float4*)(out + off) = o;
}

// ---------------- launcher ---------------------------------------------------
extern "C" void kernel_launch(void* const* d_in, const int* in_sizes, int n_in,
                              void* d_out, int out_size)
{
    const float* x   = (const float*)d_in[0];
    const float* xi  = (const float*)d_in[1];
    const float* tw  = (const float*)d_in[2];
    const float* bbw = (const float*)d_in[3];
    float* out = (float*)d_out;

    cudaFuncSetAttribute(gemm_mma_kernel,
                         cudaFuncAttributeMaxDynamicSharedMemorySize, DYN_SMEM);

    split_x_kernel<<<(B_ROWS * DIM) / (256 * 4), 256>>>((const float4*)x);
    split_w_kernel<<<dim3(DIM / 32, DIM / 32), 256>>>(tw, bbw);
    gemm_mma_kernel<<<dim3(NT, MT), 128, DYN_SMEM>>>(xi);
    stats1_kernel<<<dim3(4, 128), 256>>>();
    stats2_kernel<<<DIM / 256, 256>>>();
    final_kernel<<<dim3(DIM / (256 * 4), B_ROWS), 256>>>(out);
}